// round 14
// baseline (speedup 1.0000x reference)
#include <cuda_runtime.h>
#include <cuda_fp16.h>
#include <cstdint>

static constexpr int BATCH = 16;
static constexpr int TQ    = 2048;
static constexpr int TV    = 2048;
static constexpr int DIM   = 1024;   // d_v
static constexpr int UNITS = 1024;

// ---------------- static scratch (no runtime alloc allowed) ----------------
__device__ __half g_q_hi [(size_t)BATCH * TQ * UNITS];
__device__ __half g_q_lo [(size_t)BATCH * TQ * UNITS];
__device__ __half g_v_hi [(size_t)BATCH * TV * DIM];
__device__ __half g_v_lo [(size_t)BATCH * TV * DIM];
__device__ __half g_kt_hi[(size_t)BATCH * UNITS * TV];    // keys^T [B][UNITS][TV]
__device__ __half g_kt_lo[(size_t)BATCH * UNITS * TV];
__device__ __half g_p    [(size_t)BATCH * TQ * TV];       // alignment, fp16 hi only
__device__ __half g_w_hi [(size_t)DIM * UNITS];
__device__ __half g_w_lo [(size_t)DIM * UNITS];

// ---------------- PTX helpers ----------------
__device__ __forceinline__ void ldsm_x4(uint32_t* r, const void* p) {
    uint32_t a = (uint32_t)__cvta_generic_to_shared(p);
    asm volatile("ldmatrix.sync.aligned.m8n8.x4.shared.b16 {%0,%1,%2,%3}, [%4];"
                 : "=r"(r[0]), "=r"(r[1]), "=r"(r[2]), "=r"(r[3]) : "r"(a));
}
__device__ __forceinline__ void ldsm_x4_t(uint32_t* r, const void* p) {
    uint32_t a = (uint32_t)__cvta_generic_to_shared(p);
    asm volatile("ldmatrix.sync.aligned.m8n8.x4.trans.shared.b16 {%0,%1,%2,%3}, [%4];"
                 : "=r"(r[0]), "=r"(r[1]), "=r"(r[2]), "=r"(r[3]) : "r"(a));
}
__device__ __forceinline__ void mma_f16(float* c, const uint32_t* a, const uint32_t* b) {
    asm volatile(
        "mma.sync.aligned.m16n8k16.row.col.f32.f16.f16.f32 "
        "{%0,%1,%2,%3}, {%4,%5,%6,%7}, {%8,%9}, {%0,%1,%2,%3};"
        : "+f"(c[0]), "+f"(c[1]), "+f"(c[2]), "+f"(c[3])
        : "r"(a[0]), "r"(a[1]), "r"(a[2]), "r"(a[3]), "r"(b[0]), "r"(b[1]));
}
// fp16-accumulator MMA (2x rate on the legacy HMMA pipe)
__device__ __forceinline__ void mma_h16(uint32_t* c, const uint32_t* a, const uint32_t* b) {
    asm volatile(
        "mma.sync.aligned.m16n8k16.row.col.f16.f16.f16.f16 "
        "{%0,%1}, {%2,%3,%4,%5}, {%6,%7}, {%0,%1};"
        : "+r"(c[0]), "+r"(c[1])
        : "r"(a[0]), "r"(a[1]), "r"(a[2]), "r"(a[3]), "r"(b[0]), "r"(b[1]));
}
__device__ __forceinline__ void cpa16(void* sp, const void* gp) {
    uint32_t s = (uint32_t)__cvta_generic_to_shared(sp);
    asm volatile("cp.async.cg.shared.global [%0], [%1], 16;" :: "r"(s), "l"(gp));
}
__device__ __forceinline__ void cpa_commit() { asm volatile("cp.async.commit_group;"); }
template<int N> __device__ __forceinline__ void cpa_wait() {
    asm volatile("cp.async.wait_group %0;" :: "n"(N));
}
// fast exp: one FMUL + one MUFU.EX2
__device__ __forceinline__ float fexp(float x) {
    float r;
    asm("ex2.approx.f32 %0, %1;" : "=f"(r) : "f"(x * 1.4426950408889634f));
    return r;
}

// ---------------- split-fp16 MMA GEMM (non-trans B) ----------------
// C[M,N] = A[M,K] @ B[K,N], operands as fp16 hi/lo planes.
// NT=3: acc32 = Ah*Bh + Ah*Bl + Al*Bh       (BK=32)
// NT=1: acc32 = Ah*Bh                        (BK=64)
// NT=4: acc16 = Ah*Bl + Al*Bh (fp16 accum), epilogue does C += acc16   (BK=32)
// OUT=0: fp32 C store.  OUT=1: transposed hi/lo fp16 planes + bias (keys GEMM).
#define BM 128
#define BN 128
#define LDBN 136    // B tile row stride ([BK][136] fp16)

template<int NT, int OUT>
__global__ __launch_bounds__(256, 2)
void mma_gemm(const __half* __restrict__ Ahi, const __half* __restrict__ Alo,
              const __half* __restrict__ Bhi, const __half* __restrict__ Blo,
              float* __restrict__ C,
              __half* __restrict__ Chi, __half* __restrict__ Clo,
              const float* __restrict__ bias,
              int N, int K,
              long long sA, long long sB, long long sC)
{
    constexpr bool DUAL    = (NT != 1);
    constexpr int BKK      = (NT == 1) ? 64 : 32;
    constexpr int KSTEPS   = BKK / 16;
    constexpr int LDAx     = BKK + 8;            // 40 or 72 (conflict-free ldmatrix)
    constexpr int A_PL     = 128 * LDAx;
    constexpr int B_PL     = BKK * LDBN;
    constexpr int A_PLANES = DUAL ? 2 : 1;
    constexpr int B_PLANES = DUAL ? 2 : 1;
    constexpr int STAGE_ELEMS = A_PLANES * A_PL + B_PLANES * B_PL;  // 18944 / 17920
    constexpr int NSTAGES  = 3;
    constexpr int ACH = 128 * BKK / 8;           // A chunks per plane
    constexpr int CPR = BKK / 8;                 // chunks per A row
    constexpr int BCH = BKK * 128 / 8;           // B chunks per plane

    extern __shared__ __half sm[];

    const int tid  = threadIdx.x;
    const int lane = tid & 31;
    const int wid  = tid >> 5;
    const int wm   = (wid >> 2) * 64;
    const int wn   = (wid & 3) * 32;

    const int row0 = blockIdx.y * BM;
    const int col0 = blockIdx.x * BN;
    const long long zC = (long long)blockIdx.z * sC;
    Ahi += (long long)blockIdx.z * sA;
    if (DUAL) Alo += (long long)blockIdx.z * sA;
    Bhi += (long long)blockIdx.z * sB;
    if (DUAL) Blo += (long long)blockIdx.z * sB;

    float    acc[4][4][4]   = {};   // used by NT=1,3
    uint32_t acc16[4][4][2] = {};   // used by NT=4 (fp16x2 pairs, zero = +0)

    auto load_stage = [&](int s, int k0) {
        __half* base = sm + s * STAGE_ELEMS;
        __half* a_hi = base;
        __half* a_lo = base + A_PL;
        __half* b_hi = base + A_PLANES * A_PL;
        __half* b_lo = b_hi + B_PL;
        #pragma unroll
        for (int c = tid; c < ACH; c += 256) {
            int r = c / CPR, kc = (c % CPR) * 8;
            long long g = (long long)(row0 + r) * K + k0 + kc;
            cpa16(a_hi + r * LDAx + kc, Ahi + g);
            if (DUAL) cpa16(a_lo + r * LDAx + kc, Alo + g);
        }
        #pragma unroll
        for (int c = tid; c < BCH; c += 256) {
            int r = c >> 4, nc = (c & 15) * 8;
            long long g = (long long)(k0 + r) * N + col0 + nc;
            cpa16(b_hi + r * LDBN + nc, Bhi + g);
            if (DUAL) cpa16(b_lo + r * LDBN + nc, Blo + g);
        }
    };

    const int KT = K / BKK;
    #pragma unroll
    for (int s = 0; s < NSTAGES - 1; ++s) {
        load_stage(s, s * BKK);
        cpa_commit();
    }

    for (int kt = 0; kt < KT; ++kt) {
        if      (kt + 1 < KT) cpa_wait<1>();
        else                  cpa_wait<0>();
        __syncthreads();

        const bool do_load = (kt + NSTAGES - 1 < KT);
        const int  ld_s    = (kt + NSTAGES - 1) % NSTAGES;
        const int  ld_k    = (kt + NSTAGES - 1) * BKK;

        const __half* base = sm + (kt % NSTAGES) * STAGE_ELEMS;
        const __half* a_hi = base;
        const __half* a_lo = base + A_PL;
        const __half* b_hi = base + A_PLANES * A_PL;
        const __half* b_lo = b_hi + B_PL;

        #pragma unroll
        for (int ks = 0; ks < KSTEPS; ++ks) {
            const int kc = ks * 16;
            uint32_t bh[2][4], bl[2][4];
            #pragma unroll
            for (int p = 0; p < 2; ++p) {
                int r = kc + (lane & 7) + ((lane >> 3) & 1) * 8;
                int c = wn + p * 16 + ((lane >> 4) & 1) * 8;
                ldsm_x4_t(bh[p], b_hi + r * LDBN + c);
                if (DUAL) ldsm_x4_t(bl[p], b_lo + r * LDBN + c);
            }
            uint32_t ah[4][4];
            #pragma unroll
            for (int mi = 0; mi < 4; ++mi) {
                int r = wm + mi * 16 + (lane & 15);
                int c = kc + ((lane >> 4) & 1) * 8;
                ldsm_x4(ah[mi], a_hi + r * LDAx + c);
            }
            if (NT != 4) {
                // main term: Ah*Bh (fp32 acc)
                #pragma unroll
                for (int mi = 0; mi < 4; ++mi)
                    #pragma unroll
                    for (int ni = 0; ni < 4; ++ni)
                        mma_f16(acc[mi][ni], ah[mi], &bh[ni >> 1][(ni & 1) * 2]);
            } else {
                // correction term 1: Ah*Bl (fp16 acc)
                #pragma unroll
                for (int mi = 0; mi < 4; ++mi)
                    #pragma unroll
                    for (int ni = 0; ni < 4; ++ni)
                        mma_h16(acc16[mi][ni], ah[mi], &bl[ni >> 1][(ni & 1) * 2]);
            }

            // interleave next-stage cp.async behind the MMA stream
            if (ks == 0 && do_load) {
                load_stage(ld_s, ld_k);
                cpa_commit();
            }

            if (NT == 3) {
                uint32_t al[4][4];
                #pragma unroll
                for (int mi = 0; mi < 4; ++mi) {
                    int r = wm + mi * 16 + (lane & 15);
                    int c = kc + ((lane >> 4) & 1) * 8;
                    ldsm_x4(al[mi], a_lo + r * LDAx + c);
                }
                #pragma unroll
                for (int mi = 0; mi < 4; ++mi)
                    #pragma unroll
                    for (int ni = 0; ni < 4; ++ni)
                        mma_f16(acc[mi][ni], ah[mi], &bl[ni >> 1][(ni & 1) * 2]);
                #pragma unroll
                for (int mi = 0; mi < 4; ++mi)
                    #pragma unroll
                    for (int ni = 0; ni < 4; ++ni)
                        mma_f16(acc[mi][ni], al[mi], &bh[ni >> 1][(ni & 1) * 2]);
            }
            if (NT == 4) {
                uint32_t al[4][4];
                #pragma unroll
                for (int mi = 0; mi < 4; ++mi) {
                    int r = wm + mi * 16 + (lane & 15);
                    int c = kc + ((lane >> 4) & 1) * 8;
                    ldsm_x4(al[mi], a_lo + r * LDAx + c);
                }
                // correction term 2: Al*Bh (fp16 acc)
                #pragma unroll
                for (int mi = 0; mi < 4; ++mi)
                    #pragma unroll
                    for (int ni = 0; ni < 4; ++ni)
                        mma_h16(acc16[mi][ni], al[mi], &bh[ni >> 1][(ni & 1) * 2]);
            }
        }
    }

    if (NT == 4) {
        // accumulate corrections into existing fp32 C
        #pragma unroll
        for (int mi = 0; mi < 4; ++mi) {
            #pragma unroll
            for (int ni = 0; ni < 4; ++ni) {
                int r0 = row0 + wm + mi * 16 + (lane >> 2);
                int cc = col0 + wn + ni * 8 + (lane & 3) * 2;
                #pragma unroll
                for (int h = 0; h < 2; ++h) {
                    long long r = r0 + h * 8;
                    float2* pc = reinterpret_cast<float2*>(C + zC + r * N + cc);
                    float2 o = *pc;
                    __half2 hv = *reinterpret_cast<__half2*>(&acc16[mi][ni][h]);
                    o.x += __half2float(hv.x);
                    o.y += __half2float(hv.y);
                    *pc = o;
                }
            }
        }
    } else if (OUT == 0) {
        // fp32 epilogue
        #pragma unroll
        for (int mi = 0; mi < 4; ++mi) {
            #pragma unroll
            for (int ni = 0; ni < 4; ++ni) {
                int r0 = row0 + wm + mi * 16 + (lane >> 2);
                int cc = col0 + wn + ni * 8 + (lane & 3) * 2;
                #pragma unroll
                for (int h = 0; h < 2; ++h) {
                    long long r = r0 + h * 8;
                    *reinterpret_cast<float2*>(C + zC + r * N + cc) =
                        make_float2(acc[mi][ni][h * 2 + 0], acc[mi][ni][h * 2 + 1]);
                }
            }
        }
    } else {
        // transposed split epilogue: emit Chi/Clo[(batch)][u][t] with bias.
        __syncthreads();
        float* tw = reinterpret_cast<float*>(sm) + wid * (64 * 33);
        #pragma unroll
        for (int mi = 0; mi < 4; ++mi)
            #pragma unroll
            for (int ni = 0; ni < 4; ++ni)
                #pragma unroll
                for (int h = 0; h < 2; ++h) {
                    int lr = mi * 16 + (lane >> 2) + h * 8;
                    int lc = ni * 8 + (lane & 3) * 2;
                    tw[lr * 33 + lc]     = acc[mi][ni][h * 2 + 0];
                    tw[lr * 33 + lc + 1] = acc[mi][ni][h * 2 + 1];
                }
        __syncwarp();
        const int batch = row0 / TV;
        const int t0    = (row0 % TV) + wm + 2 * lane;
        const long long zb = (long long)batch * UNITS * TV;
        #pragma unroll 4
        for (int u = 0; u < 32; ++u) {
            int gu = col0 + wn + u;
            float bz = bias[gu];
            float v0 = tw[(2 * lane)     * 33 + u] + bz;
            float v1 = tw[(2 * lane + 1) * 33 + u] + bz;
            __half h0 = __float2half_rn(v0), h1 = __float2half_rn(v1);
            __half l0 = __float2half_rn(v0 - __half2float(h0));
            __half l1 = __float2half_rn(v1 - __half2float(h1));
            long long o = zb + (long long)gu * TV + t0;
            *reinterpret_cast<__half2*>(Chi + o) = __halves2half2(h0, h1);
            *reinterpret_cast<__half2*>(Clo + o) = __halves2half2(l0, l1);
        }
    }
}

// smem sizes per instantiation (bytes)
#define SMEM3 (3 * 18944 * 2)   // 113664 (NT=3, NT=4)
#define SMEM1 (3 * 17920 * 2)   // 107520 (NT=1)

// ---------------- fp32 -> fp16 hi/lo split ----------------
__global__ __launch_bounds__(256)
void split_kernel(const float4* __restrict__ src,
                  __half2* __restrict__ hi, __half2* __restrict__ lo,
                  long long n4)
{
    long long i = (long long)blockIdx.x * 256 + threadIdx.x;
    if (i >= n4) return;
    float4 v = src[i];
    __half h0 = __float2half_rn(v.x), h1 = __float2half_rn(v.y);
    __half h2 = __float2half_rn(v.z), h3 = __float2half_rn(v.w);
    hi[2 * i]     = __halves2half2(h0, h1);
    hi[2 * i + 1] = __halves2half2(h2, h3);
    lo[2 * i]     = __halves2half2(__float2half_rn(v.x - __half2float(h0)),
                                   __float2half_rn(v.y - __half2float(h1)));
    lo[2 * i + 1] = __halves2half2(__float2half_rn(v.z - __half2float(h2)),
                                   __float2half_rn(v.w - __half2float(h3)));
}

// ---------------- softmax (in-place fp32) + fp16 P emit, vectorized ----------------
__global__ __launch_bounds__(256)
void softmax_kernel(float* __restrict__ S, __half* __restrict__ P)
{
    long long rowoff = (long long)blockIdx.x * TV;
    float4* p4 = reinterpret_cast<float4*>(S + rowoff);
    __half2* p2 = reinterpret_cast<__half2*>(P + rowoff);
    const int tid = threadIdx.x;

    float4 v[2];
    v[0] = p4[tid];
    v[1] = p4[tid + 256];
    float m = fmaxf(fmaxf(fmaxf(v[0].x, v[0].y), fmaxf(v[0].z, v[0].w)),
                    fmaxf(fmaxf(v[1].x, v[1].y), fmaxf(v[1].z, v[1].w)));

    __shared__ float red[8];
    #pragma unroll
    for (int o = 16; o > 0; o >>= 1) m = fmaxf(m, __shfl_xor_sync(0xffffffffu, m, o));
    if ((tid & 31) == 0) red[tid >> 5] = m;
    __syncthreads();
    m = red[0];
    #pragma unroll
    for (int w = 1; w < 8; ++w) m = fmaxf(m, red[w]);
    __syncthreads();

    float s = 0.f;
    #pragma unroll
    for (int i = 0; i < 2; ++i) {
        v[i].x = fexp(v[i].x - m); s += v[i].x;
        v[i].y = fexp(v[i].y - m); s += v[i].y;
        v[i].z = fexp(v[i].z - m); s += v[i].z;
        v[i].w = fexp(v[i].w - m); s += v[i].w;
    }
    #pragma unroll
    for (int o = 16; o > 0; o >>= 1) s += __shfl_xor_sync(0xffffffffu, s, o);
    if ((tid & 31) == 0) red[tid >> 5] = s;
    __syncthreads();
    s = 0.f;
    #pragma unroll
    for (int w = 0; w < 8; ++w) s += red[w];

    const float inv = 1.0f / s;
    #pragma unroll
    for (int i = 0; i < 2; ++i) {
        v[i].x *= inv; v[i].y *= inv; v[i].z *= inv; v[i].w *= inv;
        p4[tid + i * 256] = v[i];
        p2[2 * (tid + i * 256)]     = __floats2half2_rn(v[i].x, v[i].y);
        p2[2 * (tid + i * 256) + 1] = __floats2half2_rn(v[i].z, v[i].w);
    }
}

// ---------------- launch ----------------
extern "C" void kernel_launch(void* const* d_in, const int* in_sizes, int n_in,
                              void* d_out, int out_size)
{
    const float* query  = (const float*)d_in[0];  // [B, Tq, UNITS]
    const float* values = (const float*)d_in[1];  // [B, Tv, D]
    const float* Wk     = (const float*)d_in[2];  // [D, UNITS]
    const float* Wb     = (const float*)d_in[3];  // [UNITS]

    float* ctx   = (float*)d_out;                        // [B, Tq, D]
    float* align = ctx + (size_t)BATCH * TQ * DIM;       // [B, Tq, Tv]

    __half *q_hi, *q_lo, *v_hi, *v_lo, *kt_hi, *kt_lo, *pp, *w_hi, *w_lo;
    cudaGetSymbolAddress((void**)&q_hi,  g_q_hi);
    cudaGetSymbolAddress((void**)&q_lo,  g_q_lo);
    cudaGetSymbolAddress((void**)&v_hi,  g_v_hi);
    cudaGetSymbolAddress((void**)&v_lo,  g_v_lo);
    cudaGetSymbolAddress((void**)&kt_hi, g_kt_hi);
    cudaGetSymbolAddress((void**)&kt_lo, g_kt_lo);
    cudaGetSymbolAddress((void**)&pp,    g_p);
    cudaGetSymbolAddress((void**)&w_hi,  g_w_hi);
    cudaGetSymbolAddress((void**)&w_lo,  g_w_lo);

    cudaFuncSetAttribute(mma_gemm<3, 1>, cudaFuncAttributeMaxDynamicSharedMemorySize, SMEM3);
    cudaFuncSetAttribute(mma_gemm<4, 0>, cudaFuncAttributeMaxDynamicSharedMemorySize, SMEM3);
    cudaFuncSetAttribute(mma_gemm<1, 0>, cudaFuncAttributeMaxDynamicSharedMemorySize, SMEM1);

    // 0) split inputs to fp16 hi/lo planes
    {
        long long nq = (long long)BATCH * TQ * UNITS / 4;
        split_kernel<<<(unsigned)((nq + 255) / 256), 256>>>(
            (const float4*)query, (__half2*)q_hi, (__half2*)q_lo, nq);
        long long nv = (long long)BATCH * TV * DIM / 4;
        split_kernel<<<(unsigned)((nv + 255) / 256), 256>>>(
            (const float4*)values, (__half2*)v_hi, (__half2*)v_lo, nv);
        long long nw = (long long)DIM * UNITS / 4;
        split_kernel<<<(unsigned)((nw + 255) / 256), 256>>>(
            (const float4*)Wk, (__half2*)w_hi, (__half2*)w_lo, nw);
    }

    // 1) keys = values @ W + bias -> keys^T fp16 hi/lo planes (3-term, fused transpose-split)
    {
        dim3 grid(UNITS / BN, (BATCH * TV) / BM, 1);
        mma_gemm<3, 1><<<grid, 256, SMEM3>>>(
            v_hi, v_lo, w_hi, w_lo,
            nullptr, kt_hi, kt_lo, Wb,
            UNITS, DIM, 0LL, 0LL, 0LL);
    }

    // 2a) scores main term: Qh @ Kth -> fp32 align   (single-term, BK=64)
    {
        dim3 grid(TV / BN, TQ / BM, BATCH);
        mma_gemm<1, 0><<<grid, 256, SMEM1>>>(
            q_hi, nullptr, kt_hi, nullptr,
            align, nullptr, nullptr, nullptr,
            TV, UNITS,
            (long long)TQ * UNITS, (long long)UNITS * TV, (long long)TQ * TV);
    }

    // 2b) scores corrections: Qh@Ktl + Ql@Kth with fp16 accumulators -> align +=
    {
        dim3 grid(TV / BN, TQ / BM, BATCH);
        mma_gemm<4, 0><<<grid, 256, SMEM3>>>(
            q_hi, q_lo, kt_hi, kt_lo,
            align, nullptr, nullptr, nullptr,
            TV, UNITS,
            (long long)TQ * UNITS, (long long)UNITS * TV, (long long)TQ * TV);
    }

    // 3) softmax in place + emit fp16 P plane
    softmax_kernel<<<BATCH * TQ, 256>>>(align, pp);

    // 4) context = P @ values -> fp32 ctx   (single-term: Ph * Vh, BK=64)
    {
        dim3 grid(DIM / BN, TQ / BM, BATCH);
        mma_gemm<1, 0><<<grid, 256, SMEM1>>>(
            pp, nullptr, v_hi, nullptr,
            ctx, nullptr, nullptr, nullptr,
            DIM, TV,
            (long long)TQ * TV, (long long)TV * DIM, (long long)TQ * DIM);
    }
}

// round 15
// speedup vs baseline: 1.1803x; 1.1803x over previous
#include <cuda_runtime.h>
#include <cuda_fp16.h>
#include <cstdint>

static constexpr int BATCH = 16;
static constexpr int TQ    = 2048;
static constexpr int TV    = 2048;
static constexpr int DIM   = 1024;   // d_v
static constexpr int UNITS = 1024;

// ---------------- static scratch (no runtime alloc allowed) ----------------
__device__ __half g_q_hi [(size_t)BATCH * TQ * UNITS];
__device__ __half g_q_lo [(size_t)BATCH * TQ * UNITS];
__device__ __half g_v_hi [(size_t)BATCH * TV * DIM];
__device__ __half g_v_lo [(size_t)BATCH * TV * DIM];
__device__ __half g_kt_hi[(size_t)BATCH * UNITS * TV];    // keys^T [B][UNITS][TV]
__device__ __half g_kt_lo[(size_t)BATCH * UNITS * TV];
__device__ __half g_p    [(size_t)BATCH * TQ * TV];       // alignment, fp16 hi only
__device__ __half g_w_hi [(size_t)DIM * UNITS];
__device__ __half g_w_lo [(size_t)DIM * UNITS];

// ---------------- PTX helpers ----------------
__device__ __forceinline__ void ldsm_x4(uint32_t* r, const void* p) {
    uint32_t a = (uint32_t)__cvta_generic_to_shared(p);
    asm volatile("ldmatrix.sync.aligned.m8n8.x4.shared.b16 {%0,%1,%2,%3}, [%4];"
                 : "=r"(r[0]), "=r"(r[1]), "=r"(r[2]), "=r"(r[3]) : "r"(a));
}
__device__ __forceinline__ void ldsm_x4_t(uint32_t* r, const void* p) {
    uint32_t a = (uint32_t)__cvta_generic_to_shared(p);
    asm volatile("ldmatrix.sync.aligned.m8n8.x4.trans.shared.b16 {%0,%1,%2,%3}, [%4];"
                 : "=r"(r[0]), "=r"(r[1]), "=r"(r[2]), "=r"(r[3]) : "r"(a));
}
__device__ __forceinline__ void mma_f16(float* c, const uint32_t* a, const uint32_t* b) {
    asm volatile(
        "mma.sync.aligned.m16n8k16.row.col.f32.f16.f16.f32 "
        "{%0,%1,%2,%3}, {%4,%5,%6,%7}, {%8,%9}, {%0,%1,%2,%3};"
        : "+f"(c[0]), "+f"(c[1]), "+f"(c[2]), "+f"(c[3])
        : "r"(a[0]), "r"(a[1]), "r"(a[2]), "r"(a[3]), "r"(b[0]), "r"(b[1]));
}
__device__ __forceinline__ void cpa16(void* sp, const void* gp) {
    uint32_t s = (uint32_t)__cvta_generic_to_shared(sp);
    asm volatile("cp.async.cg.shared.global [%0], [%1], 16;" :: "r"(s), "l"(gp));
}
__device__ __forceinline__ void cpa_commit() { asm volatile("cp.async.commit_group;"); }
template<int N> __device__ __forceinline__ void cpa_wait() {
    asm volatile("cp.async.wait_group %0;" :: "n"(N));
}
// fast exp: one FMUL + one MUFU.EX2
__device__ __forceinline__ float fexp(float x) {
    float r;
    asm("ex2.approx.f32 %0, %1;" : "=f"(r) : "f"(x * 1.4426950408889634f));
    return r;
}

// ---------------- split-fp16 MMA GEMM (non-trans B) ----------------
// C[M,N] = A[M,K] @ B[K,N], operands as fp16 hi/lo planes.
// NT=3: acc = Ah*Bh + Ah*Bl + Al*Bh   (BK=32, 3-stage pipeline)
// NT=1: acc = Ah*Bh, single plane each side (BK=64, 3-stage pipeline)
// OUT=0: fp32 C.  OUT=1: transposed hi/lo fp16 planes + bias (keys GEMM).
// Next-stage cp.async is split: A planes issued after ks==0's first MMA batch,
// B planes after ks==1's first MMA batch (smaller LSU bursts inside the MMA stream).
#define BM 128
#define BN 128
#define LDBN 136    // B tile row stride ([BK][136] fp16)

template<int NT, int OUT>
__global__ __launch_bounds__(256, 2)
void mma_gemm(const __half* __restrict__ Ahi, const __half* __restrict__ Alo,
              const __half* __restrict__ Bhi, const __half* __restrict__ Blo,
              float* __restrict__ C,
              __half* __restrict__ Chi, __half* __restrict__ Clo,
              const float* __restrict__ bias,
              int N, int K,
              long long sA, long long sB, long long sC)
{
    constexpr bool DUAL    = (NT == 3);
    constexpr int BKK      = (NT == 1) ? 64 : 32;
    constexpr int KSTEPS   = BKK / 16;
    constexpr int LDAx     = BKK + 8;            // 40 or 72 (conflict-free ldmatrix)
    constexpr int A_PL     = 128 * LDAx;
    constexpr int B_PL     = BKK * LDBN;
    constexpr int A_PLANES = DUAL ? 2 : 1;
    constexpr int B_PLANES = DUAL ? 2 : 1;
    constexpr int STAGE_ELEMS = A_PLANES * A_PL + B_PLANES * B_PL;  // 18944 / 17920
    constexpr int NSTAGES  = 3;
    constexpr int ACH = 128 * BKK / 8;           // A chunks per plane
    constexpr int CPR = BKK / 8;                 // chunks per A row
    constexpr int BCH = BKK * 128 / 8;           // B chunks per plane

    extern __shared__ __half sm[];

    const int tid  = threadIdx.x;
    const int lane = tid & 31;
    const int wid  = tid >> 5;
    const int wm   = (wid >> 2) * 64;
    const int wn   = (wid & 3) * 32;

    const int row0 = blockIdx.y * BM;
    const int col0 = blockIdx.x * BN;
    const long long zC = (long long)blockIdx.z * sC;
    Ahi += (long long)blockIdx.z * sA;
    if (DUAL) Alo += (long long)blockIdx.z * sA;
    Bhi += (long long)blockIdx.z * sB;
    if (DUAL) Blo += (long long)blockIdx.z * sB;

    float acc[4][4][4] = {};

    auto load_A = [&](int s, int k0) {
        __half* base = sm + s * STAGE_ELEMS;
        __half* a_hi = base;
        __half* a_lo = base + A_PL;
        #pragma unroll
        for (int c = tid; c < ACH; c += 256) {
            int r = c / CPR, kc = (c % CPR) * 8;
            long long g = (long long)(row0 + r) * K + k0 + kc;
            cpa16(a_hi + r * LDAx + kc, Ahi + g);
            if (DUAL) cpa16(a_lo + r * LDAx + kc, Alo + g);
        }
    };
    auto load_B = [&](int s, int k0) {
        __half* base = sm + s * STAGE_ELEMS;
        __half* b_hi = base + A_PLANES * A_PL;
        __half* b_lo = b_hi + B_PL;
        #pragma unroll
        for (int c = tid; c < BCH; c += 256) {
            int r = c >> 4, nc = (c & 15) * 8;
            long long g = (long long)(k0 + r) * N + col0 + nc;
            cpa16(b_hi + r * LDBN + nc, Bhi + g);
            if (DUAL) cpa16(b_lo + r * LDBN + nc, Blo + g);
        }
    };

    const int KT = K / BKK;
    #pragma unroll
    for (int s = 0; s < NSTAGES - 1; ++s) {
        load_A(s, s * BKK);
        load_B(s, s * BKK);
        cpa_commit();
    }

    for (int kt = 0; kt < KT; ++kt) {
        if      (kt + 1 < KT) cpa_wait<1>();
        else                  cpa_wait<0>();
        __syncthreads();

        const bool do_load = (kt + NSTAGES - 1 < KT);
        const int  ld_s    = (kt + NSTAGES - 1) % NSTAGES;
        const int  ld_k    = (kt + NSTAGES - 1) * BKK;

        const __half* base = sm + (kt % NSTAGES) * STAGE_ELEMS;
        const __half* a_hi = base;
        const __half* a_lo = base + A_PL;
        const __half* b_hi = base + A_PLANES * A_PL;
        const __half* b_lo = b_hi + B_PL;

        #pragma unroll
        for (int ks = 0; ks < KSTEPS; ++ks) {
            const int kc = ks * 16;
            uint32_t bh[2][4], bl[2][4];
            #pragma unroll
            for (int p = 0; p < 2; ++p) {
                int r = kc + (lane & 7) + ((lane >> 3) & 1) * 8;
                int c = wn + p * 16 + ((lane >> 4) & 1) * 8;
                ldsm_x4_t(bh[p], b_hi + r * LDBN + c);
                if (DUAL) ldsm_x4_t(bl[p], b_lo + r * LDBN + c);
            }
            uint32_t ah[4][4];
            #pragma unroll
            for (int mi = 0; mi < 4; ++mi) {
                int r = wm + mi * 16 + (lane & 15);
                int c = kc + ((lane >> 4) & 1) * 8;
                ldsm_x4(ah[mi], a_hi + r * LDAx + c);
            }
            // term 1: Ah*Bh
            #pragma unroll
            for (int mi = 0; mi < 4; ++mi)
                #pragma unroll
                for (int ni = 0; ni < 4; ++ni)
                    mma_f16(acc[mi][ni], ah[mi], &bh[ni >> 1][(ni & 1) * 2]);

            // interleave next-stage cp.async in two smaller bursts
            if (do_load) {
                if (ks == 0) load_A(ld_s, ld_k);
                if (ks == 1) {
                    load_B(ld_s, ld_k);
                    cpa_commit();
                }
            }

            if (DUAL) {
                uint32_t al[4][4];
                #pragma unroll
                for (int mi = 0; mi < 4; ++mi) {
                    int r = wm + mi * 16 + (lane & 15);
                    int c = kc + ((lane >> 4) & 1) * 8;
                    ldsm_x4(al[mi], a_lo + r * LDAx + c);
                }
                // term 2: Ah*Bl
                #pragma unroll
                for (int mi = 0; mi < 4; ++mi)
                    #pragma unroll
                    for (int ni = 0; ni < 4; ++ni)
                        mma_f16(acc[mi][ni], ah[mi], &bl[ni >> 1][(ni & 1) * 2]);
                // term 3: Al*Bh
                #pragma unroll
                for (int mi = 0; mi < 4; ++mi)
                    #pragma unroll
                    for (int ni = 0; ni < 4; ++ni)
                        mma_f16(acc[mi][ni], al[mi], &bh[ni >> 1][(ni & 1) * 2]);
            }
        }
    }

    if (OUT == 0) {
        // fp32 epilogue
        #pragma unroll
        for (int mi = 0; mi < 4; ++mi) {
            #pragma unroll
            for (int ni = 0; ni < 4; ++ni) {
                int r0 = row0 + wm + mi * 16 + (lane >> 2);
                int cc = col0 + wn + ni * 8 + (lane & 3) * 2;
                #pragma unroll
                for (int h = 0; h < 2; ++h) {
                    long long r = r0 + h * 8;
                    *reinterpret_cast<float2*>(C + zC + r * N + cc) =
                        make_float2(acc[mi][ni][h * 2 + 0], acc[mi][ni][h * 2 + 1]);
                }
            }
        }
    } else {
        // transposed split epilogue: emit Chi/Clo[(batch)][u][t] with bias.
        __syncthreads();
        float* tw = reinterpret_cast<float*>(sm) + wid * (64 * 33);
        #pragma unroll
        for (int mi = 0; mi < 4; ++mi)
            #pragma unroll
            for (int ni = 0; ni < 4; ++ni)
                #pragma unroll
                for (int h = 0; h < 2; ++h) {
                    int lr = mi * 16 + (lane >> 2) + h * 8;
                    int lc = ni * 8 + (lane & 3) * 2;
                    tw[lr * 33 + lc]     = acc[mi][ni][h * 2 + 0];
                    tw[lr * 33 + lc + 1] = acc[mi][ni][h * 2 + 1];
                }
        __syncwarp();
        const int batch = row0 / TV;
        const int t0    = (row0 % TV) + wm + 2 * lane;
        const long long zb = (long long)batch * UNITS * TV;
        #pragma unroll 4
        for (int u = 0; u < 32; ++u) {
            int gu = col0 + wn + u;
            float bz = bias[gu];
            float v0 = tw[(2 * lane)     * 33 + u] + bz;
            float v1 = tw[(2 * lane + 1) * 33 + u] + bz;
            __half h0 = __float2half_rn(v0), h1 = __float2half_rn(v1);
            __half l0 = __float2half_rn(v0 - __half2float(h0));
            __half l1 = __float2half_rn(v1 - __half2float(h1));
            long long o = zb + (long long)gu * TV + t0;
            *reinterpret_cast<__half2*>(Chi + o) = __halves2half2(h0, h1);
            *reinterpret_cast<__half2*>(Clo + o) = __halves2half2(l0, l1);
        }
    }
}

// smem sizes per instantiation (bytes)
#define SMEM3 (3 * 18944 * 2)   // 113664
#define SMEM1 (3 * 17920 * 2)   // 107520

// ---------------- fp32 -> fp16 hi/lo split ----------------
__global__ __launch_bounds__(256)
void split_kernel(const float4* __restrict__ src,
                  __half2* __restrict__ hi, __half2* __restrict__ lo,
                  long long n4)
{
    long long i = (long long)blockIdx.x * 256 + threadIdx.x;
    if (i >= n4) return;
    float4 v = src[i];
    __half h0 = __float2half_rn(v.x), h1 = __float2half_rn(v.y);
    __half h2 = __float2half_rn(v.z), h3 = __float2half_rn(v.w);
    hi[2 * i]     = __halves2half2(h0, h1);
    hi[2 * i + 1] = __halves2half2(h2, h3);
    lo[2 * i]     = __halves2half2(__float2half_rn(v.x - __half2float(h0)),
                                   __float2half_rn(v.y - __half2float(h1)));
    lo[2 * i + 1] = __halves2half2(__float2half_rn(v.z - __half2float(h2)),
                                   __float2half_rn(v.w - __half2float(h3)));
}

// ---------------- softmax (in-place fp32) + fp16 P emit, vectorized ----------------
__global__ __launch_bounds__(256)
void softmax_kernel(float* __restrict__ S, __half* __restrict__ P)
{
    long long rowoff = (long long)blockIdx.x * TV;
    float4* p4 = reinterpret_cast<float4*>(S + rowoff);
    __half2* p2 = reinterpret_cast<__half2*>(P + rowoff);
    const int tid = threadIdx.x;

    float4 v[2];
    v[0] = p4[tid];
    v[1] = p4[tid + 256];
    float m = fmaxf(fmaxf(fmaxf(v[0].x, v[0].y), fmaxf(v[0].z, v[0].w)),
                    fmaxf(fmaxf(v[1].x, v[1].y), fmaxf(v[1].z, v[1].w)));

    __shared__ float red[8];
    #pragma unroll
    for (int o = 16; o > 0; o >>= 1) m = fmaxf(m, __shfl_xor_sync(0xffffffffu, m, o));
    if ((tid & 31) == 0) red[tid >> 5] = m;
    __syncthreads();
    m = red[0];
    #pragma unroll
    for (int w = 1; w < 8; ++w) m = fmaxf(m, red[w]);
    __syncthreads();

    float s = 0.f;
    #pragma unroll
    for (int i = 0; i < 2; ++i) {
        v[i].x = fexp(v[i].x - m); s += v[i].x;
        v[i].y = fexp(v[i].y - m); s += v[i].y;
        v[i].z = fexp(v[i].z - m); s += v[i].z;
        v[i].w = fexp(v[i].w - m); s += v[i].w;
    }
    #pragma unroll
    for (int o = 16; o > 0; o >>= 1) s += __shfl_xor_sync(0xffffffffu, s, o);
    if ((tid & 31) == 0) red[tid >> 5] = s;
    __syncthreads();
    s = 0.f;
    #pragma unroll
    for (int w = 0; w < 8; ++w) s += red[w];

    const float inv = 1.0f / s;
    #pragma unroll
    for (int i = 0; i < 2; ++i) {
        v[i].x *= inv; v[i].y *= inv; v[i].z *= inv; v[i].w *= inv;
        p4[tid + i * 256] = v[i];
        p2[2 * (tid + i * 256)]     = __floats2half2_rn(v[i].x, v[i].y);
        p2[2 * (tid + i * 256) + 1] = __floats2half2_rn(v[i].z, v[i].w);
    }
}

// ---------------- launch ----------------
extern "C" void kernel_launch(void* const* d_in, const int* in_sizes, int n_in,
                              void* d_out, int out_size)
{
    const float* query  = (const float*)d_in[0];  // [B, Tq, UNITS]
    const float* values = (const float*)d_in[1];  // [B, Tv, D]
    const float* Wk     = (const float*)d_in[2];  // [D, UNITS]
    const float* Wb     = (const float*)d_in[3];  // [UNITS]

    float* ctx   = (float*)d_out;                        // [B, Tq, D]
    float* align = ctx + (size_t)BATCH * TQ * DIM;       // [B, Tq, Tv]

    __half *q_hi, *q_lo, *v_hi, *v_lo, *kt_hi, *kt_lo, *pp, *w_hi, *w_lo;
    cudaGetSymbolAddress((void**)&q_hi,  g_q_hi);
    cudaGetSymbolAddress((void**)&q_lo,  g_q_lo);
    cudaGetSymbolAddress((void**)&v_hi,  g_v_hi);
    cudaGetSymbolAddress((void**)&v_lo,  g_v_lo);
    cudaGetSymbolAddress((void**)&kt_hi, g_kt_hi);
    cudaGetSymbolAddress((void**)&kt_lo, g_kt_lo);
    cudaGetSymbolAddress((void**)&pp,    g_p);
    cudaGetSymbolAddress((void**)&w_hi,  g_w_hi);
    cudaGetSymbolAddress((void**)&w_lo,  g_w_lo);

    cudaFuncSetAttribute(mma_gemm<3, 1>, cudaFuncAttributeMaxDynamicSharedMemorySize, SMEM3);
    cudaFuncSetAttribute(mma_gemm<3, 0>, cudaFuncAttributeMaxDynamicSharedMemorySize, SMEM3);
    cudaFuncSetAttribute(mma_gemm<1, 0>, cudaFuncAttributeMaxDynamicSharedMemorySize, SMEM1);

    // 0) split inputs to fp16 hi/lo planes
    {
        long long nq = (long long)BATCH * TQ * UNITS / 4;
        split_kernel<<<(unsigned)((nq + 255) / 256), 256>>>(
            (const float4*)query, (__half2*)q_hi, (__half2*)q_lo, nq);
        long long nv = (long long)BATCH * TV * DIM / 4;
        split_kernel<<<(unsigned)((nv + 255) / 256), 256>>>(
            (const float4*)values, (__half2*)v_hi, (__half2*)v_lo, nv);
        long long nw = (long long)DIM * UNITS / 4;
        split_kernel<<<(unsigned)((nw + 255) / 256), 256>>>(
            (const float4*)Wk, (__half2*)w_hi, (__half2*)w_lo, nw);
    }

    // 1) keys = values @ W + bias -> keys^T fp16 hi/lo planes (3-term, fused transpose-split)
    {
        dim3 grid(UNITS / BN, (BATCH * TV) / BM, 1);
        mma_gemm<3, 1><<<grid, 256, SMEM3>>>(
            v_hi, v_lo, w_hi, w_lo,
            nullptr, kt_hi, kt_lo, Wb,
            UNITS, DIM, 0LL, 0LL, 0LL);
    }

    // 2) scores = query @ keys^T -> fp32 align   (3-term, fused)
    {
        dim3 grid(TV / BN, TQ / BM, BATCH);
        mma_gemm<3, 0><<<grid, 256, SMEM3>>>(
            q_hi, q_lo, kt_hi, kt_lo,
            align, nullptr, nullptr, nullptr,
            TV, UNITS,
            (long long)TQ * UNITS, (long long)UNITS * TV, (long long)TQ * TV);
    }

    // 3) softmax in place + emit fp16 P plane
    softmax_kernel<<<BATCH * TQ, 256>>>(align, pp);

    // 4) context = P @ values -> fp32 ctx   (single-term: Ph * Vh, BK=64)
    {
        dim3 grid(DIM / BN, TQ / BM, BATCH);
        mma_gemm<1, 0><<<grid, 256, SMEM1>>>(
            pp, nullptr, v_hi, nullptr,
            ctx, nullptr, nullptr, nullptr,
            DIM, TV,
            (long long)TQ * TV, (long long)TV * DIM, (long long)TQ * DIM);
    }
}